// round 1
// baseline (speedup 1.0000x reference)
#include <cuda_runtime.h>

// GEMM: out[m][d] = sum_k ecg[m*128+k] * W[d*128+k] + b[d]
// M = 196608, K = 128, N = 64. f32x2 packed FMA (FFMA2) for 2x fp32 throughput.

#define THREADS 256
#define BM 128
#define ASTRIDE 129   // float4 row stride (pad for conflict-free STS/LDS)

__device__ __forceinline__ unsigned long long ffma2(unsigned long long a,
                                                    unsigned long long b,
                                                    unsigned long long c) {
    unsigned long long d;
    asm("fma.rn.f32x2 %0, %1, %2, %3;" : "=l"(d) : "l"(a), "l"(b), "l"(c));
    return d;
}

__global__ __launch_bounds__(THREADS, 2)
void ecg_tok_gemm(const float* __restrict__ ecg,
                  const float* __restrict__ W,
                  const float* __restrict__ bias,
                  float* __restrict__ out) {
    extern __shared__ char smem_raw[];
    // Ws: [kp][d] float2, kp = 0..63 (full K=128 as 64 k-pairs), d = 0..63  -> 32768 B
    float2* Ws = reinterpret_cast<float2*>(smem_raw);
    // As: [f4][row] float4, f4 = 0..7 (BK=32 as 8 k-quads), row = 0..127, stride 129
    float4* As = reinterpret_cast<float4*>(smem_raw + 64 * 64 * sizeof(float2));

    const int tid = threadIdx.x;

    // Load full W into shared: Ws[kp*64 + d] = (W[d][2kp], W[d][2kp+1])
    for (int idx = tid; idx < 64 * 64; idx += THREADS) {
        int d  = idx >> 6;
        int kp = idx & 63;
        Ws[kp * 64 + d] = *reinterpret_cast<const float2*>(W + d * 128 + 2 * kp);
    }

    const int tx = tid & 15;        // d-tile index
    const int ty = tid >> 4;        // row-tile index
    const int r0 = ty * 8;
    const int d0 = tx * 4;
    const long long m0 = (long long)blockIdx.x * BM;

    unsigned long long acc[8][4];
    #pragma unroll
    for (int i = 0; i < 8; i++)
        #pragma unroll
        for (int j = 0; j < 4; j++) acc[i][j] = 0ull;

    __syncthreads();

    #pragma unroll
    for (int k0 = 0; k0 < 128; k0 += 32) {
        // Load A tile: 128 rows x 32 floats. 1024 float4s, 4 per thread.
        // idx: f4 fastest -> global loads coalesced (8 threads cover one row's 128B chunk)
        #pragma unroll
        for (int it = 0; it < 4; it++) {
            int idx = tid + it * THREADS;       // 0..1023
            int row = idx >> 3;
            int f4  = idx & 7;
            float4 v = *reinterpret_cast<const float4*>(
                ecg + (m0 + row) * 128 + k0 + f4 * 4);
            As[f4 * ASTRIDE + row] = v;          // stride 129*16B -> conflict-free
        }
        __syncthreads();

        const int kpbase = k0 >> 1;              // k-pair base into Ws
        #pragma unroll
        for (int f4 = 0; f4 < 8; f4++) {
            // 8 rows, each float4 = 2 k-pairs
            ulonglong2 a2[8];
            const ulonglong2* Ap =
                reinterpret_cast<const ulonglong2*>(&As[f4 * ASTRIDE + r0]);
            #pragma unroll
            for (int i = 0; i < 8; i++) a2[i] = Ap[i];

            const int kp0 = kpbase + f4 * 2;
            const unsigned long long* Wp0 =
                reinterpret_cast<const unsigned long long*>(&Ws[kp0 * 64 + d0]);
            const unsigned long long* Wp1 =
                reinterpret_cast<const unsigned long long*>(&Ws[(kp0 + 1) * 64 + d0]);

            unsigned long long w0[4], w1[4];
            #pragma unroll
            for (int j = 0; j < 4; j++) { w0[j] = Wp0[j]; w1[j] = Wp1[j]; }

            #pragma unroll
            for (int i = 0; i < 8; i++) {
                #pragma unroll
                for (int j = 0; j < 4; j++) {
                    acc[i][j] = ffma2(a2[i].x, w0[j], acc[i][j]);
                    acc[i][j] = ffma2(a2[i].y, w1[j], acc[i][j]);
                }
            }
        }
        __syncthreads();
    }

    // Epilogue: unpack f32x2 (lo = even-k partial, hi = odd-k partial), add bias.
    float4 bv = *reinterpret_cast<const float4*>(bias + d0);
    #pragma unroll
    for (int i = 0; i < 8; i++) {
        float4 o;
        {
            unsigned long long v = acc[i][0];
            o.x = __uint_as_float((unsigned)v) + __uint_as_float((unsigned)(v >> 32)) + bv.x;
        }
        {
            unsigned long long v = acc[i][1];
            o.y = __uint_as_float((unsigned)v) + __uint_as_float((unsigned)(v >> 32)) + bv.y;
        }
        {
            unsigned long long v = acc[i][2];
            o.z = __uint_as_float((unsigned)v) + __uint_as_float((unsigned)(v >> 32)) + bv.z;
        }
        {
            unsigned long long v = acc[i][3];
            o.w = __uint_as_float((unsigned)v) + __uint_as_float((unsigned)(v >> 32)) + bv.w;
        }
        *reinterpret_cast<float4*>(out + (m0 + r0 + i) * 64 + d0) = o;
    }
}

__global__ void fill_const_kernel(float* __restrict__ p, int n, float v) {
    int i = blockIdx.x * blockDim.x + threadIdx.x;
    if (i < n) p[i] = v;
}

extern "C" void kernel_launch(void* const* d_in, const int* in_sizes, int n_in,
                              void* d_out, int out_size) {
    const float* ecg = (const float*)d_in[0];   // [B, L, T] f32
    const float* W   = (const float*)d_in[1];   // [64, 128] f32
    const float* b   = (const float*)d_in[2];   // [64] f32
    float* out = (float*)d_out;

    const int M = in_sizes[0] / 128;            // total windows = B*L*N
    const long long xelems = (long long)M * 64; // X output elements

    const int smem_bytes = 64 * 64 * (int)sizeof(float2) + 8 * ASTRIDE * (int)sizeof(float4);
    cudaFuncSetAttribute(ecg_tok_gemm, cudaFuncAttributeMaxDynamicSharedMemorySize, smem_bytes);

    ecg_tok_gemm<<<M / BM, THREADS, smem_bytes>>>(ecg, W, b, out);

    // beat_intervals tail: constant BEAT_LEN = 128.0
    int rem = out_size - (int)xelems;
    if (rem > 0) {
        fill_const_kernel<<<(rem + 255) / 256, 256>>>(out + xelems, rem, 128.0f);
    }
}

// round 2
// speedup vs baseline: 1.1487x; 1.1487x over previous
#include <cuda_runtime.h>

// out[m][d] = sum_k ecg[m*128+k] * W[d*128+k] + b[d]
// M = 196608, K = 128, N = 64. Packed f32x2 FMA, 8x8 thread tile,
// conflict-free interleaved lane mapping, double-buffered A tiles.

#define THREADS 128
#define BM 128
#define ASTRIDE 129   // float4 row stride for A tiles

__device__ __forceinline__ unsigned long long ffma2(unsigned long long a,
                                                    unsigned long long b,
                                                    unsigned long long c) {
    unsigned long long d;
    asm("fma.rn.f32x2 %0, %1, %2, %3;" : "=l"(d) : "l"(a), "l"(b), "l"(c));
    return d;
}

__global__ __launch_bounds__(THREADS, 2)
void ecg_tok_gemm(const float* __restrict__ ecg,
                  const float* __restrict__ W,
                  const float* __restrict__ bias,
                  float* __restrict__ out) {
    extern __shared__ char smem_raw[];
    // Ws: [kp 0..63][d 0..63] float2 (kp = k-pair index over full K=128) -> 32 KB
    float2* Ws = reinterpret_cast<float2*>(smem_raw);
    // As: double-buffered [f4 0..7][row 0..127] float4 (one BK=32 chunk), stride 129
    float4* As0 = reinterpret_cast<float4*>(smem_raw + 64 * 64 * sizeof(float2));
    float4* As1 = As0 + 8 * ASTRIDE;

    const int tid  = threadIdx.x;
    const int warp = tid >> 5;
    const int lane = tid & 31;
    const int rg   = lane >> 3;   // 0..3 row group
    const int cg   = lane & 7;    // 0..7 col group
    const long long m0 = (long long)blockIdx.x * BM;

    // Load full W into shared: Ws[kp*64 + d] = (W[d][2kp], W[d][2kp+1])
    for (int idx = tid; idx < 64 * 64; idx += THREADS) {
        int d  = idx >> 6;
        int kp = idx & 63;
        Ws[kp * 64 + d] = *reinterpret_cast<const float2*>(W + d * 128 + 2 * kp);
    }

    // Per-thread global-load geometry: f4 = tid&7, rows = (tid>>3) + 16*t
    const int g_f4  = tid & 7;
    const int g_row = tid >> 3;
    const float* gbase = ecg + (m0 + g_row) * 128 + g_f4 * 4;

    // Prologue: stage chunk 0
    float4 stage[8];
    #pragma unroll
    for (int t = 0; t < 8; t++)
        stage[t] = *reinterpret_cast<const float4*>(gbase + (long long)t * 16 * 128);

    unsigned long long acc[8][8];
    #pragma unroll
    for (int i = 0; i < 8; i++)
        #pragma unroll
        for (int j = 0; j < 8; j++) acc[i][j] = 0ull;

    const int rbase = warp * 32 + 2 * rg;   // lane's base row within block

    for (int c = 0; c < 4; c++) {
        float4* As = (c & 1) ? As1 : As0;

        // STS staged chunk
        #pragma unroll
        for (int t = 0; t < 8; t++)
            As[g_f4 * ASTRIDE + g_row + 16 * t] = stage[t];

        __syncthreads();   // single barrier per chunk (orders STS->compute and
                           // transitively next STS vs prev compute)

        // Prefetch next chunk while computing this one
        if (c < 3) {
            #pragma unroll
            for (int t = 0; t < 8; t++)
                stage[t] = *reinterpret_cast<const float4*>(
                    gbase + (c + 1) * 32 + (long long)t * 16 * 128);
        }

        const int kpc = c * 16;   // global k-pair base for this chunk
        #pragma unroll
        for (int f4 = 0; f4 < 8; f4++) {
            const int kp0 = kpc + 2 * f4;

            // w: lane's 8 d-values for kp0 and kp0+1 (4 LDS.128 each, conflict-free)
            ulonglong2 w0[4], w1[4];
            #pragma unroll
            for (int j = 0; j < 4; j++) {
                w0[j] = *reinterpret_cast<const ulonglong2*>(
                            Ws + (kp0 * 64 + j * 16 + 2 * cg));
                w1[j] = *reinterpret_cast<const ulonglong2*>(
                            Ws + ((kp0 + 1) * 64 + j * 16 + 2 * cg));
            }

            const float4* Ap = As + f4 * ASTRIDE + rbase;
            #pragma unroll
            for (int i = 0; i < 4; i++) {
                // two adjacent rows: p=0,1 (each LDS.128: 4 distinct x 8-bcast)
                ulonglong2 a0 = *reinterpret_cast<const ulonglong2*>(Ap + i * 8);
                ulonglong2 a1 = *reinterpret_cast<const ulonglong2*>(Ap + i * 8 + 1);
                #pragma unroll
                for (int j = 0; j < 4; j++) {
                    acc[2*i  ][2*j  ] = ffma2(a0.x, w0[j].x, acc[2*i  ][2*j  ]);
                    acc[2*i  ][2*j  ] = ffma2(a0.y, w1[j].x, acc[2*i  ][2*j  ]);
                    acc[2*i  ][2*j+1] = ffma2(a0.x, w0[j].y, acc[2*i  ][2*j+1]);
                    acc[2*i  ][2*j+1] = ffma2(a0.y, w1[j].y, acc[2*i  ][2*j+1]);
                    acc[2*i+1][2*j  ] = ffma2(a1.x, w0[j].x, acc[2*i+1][2*j  ]);
                    acc[2*i+1][2*j  ] = ffma2(a1.y, w1[j].x, acc[2*i+1][2*j  ]);
                    acc[2*i+1][2*j+1] = ffma2(a1.x, w0[j].y, acc[2*i+1][2*j+1]);
                    acc[2*i+1][2*j+1] = ffma2(a1.y, w1[j].y, acc[2*i+1][2*j+1]);
                }
            }
        }
        __syncthreads();   // protect As buffer reuse (c and c+2 share a buffer)
    }

    // Epilogue: unpack f32x2 (even-k + odd-k partials), add bias, store.
    float2 bv[4];
    #pragma unroll
    for (int j = 0; j < 4; j++)
        bv[j] = *reinterpret_cast<const float2*>(bias + j * 16 + 2 * cg);

    #pragma unroll
    for (int i = 0; i < 4; i++) {
        #pragma unroll
        for (int p = 0; p < 2; p++) {
            long long row = m0 + rbase + i * 8 + p;
            float* orow = out + row * 64;
            #pragma unroll
            for (int j = 0; j < 4; j++) {
                unsigned long long v0 = acc[2*i+p][2*j];
                unsigned long long v1 = acc[2*i+p][2*j+1];
                float2 o;
                o.x = __uint_as_float((unsigned)v0) +
                      __uint_as_float((unsigned)(v0 >> 32)) + bv[j].x;
                o.y = __uint_as_float((unsigned)v1) +
                      __uint_as_float((unsigned)(v1 >> 32)) + bv[j].y;
                *reinterpret_cast<float2*>(orow + j * 16 + 2 * cg) = o;
            }
        }
    }
}

__global__ void fill_const_kernel(float* __restrict__ p, int n, float v) {
    int i = blockIdx.x * blockDim.x + threadIdx.x;
    if (i < n) p[i] = v;
}

extern "C" void kernel_launch(void* const* d_in, const int* in_sizes, int n_in,
                              void* d_out, int out_size) {
    const float* ecg = (const float*)d_in[0];   // [B, L, T] f32
    const float* W   = (const float*)d_in[1];   // [64, 128] f32
    const float* b   = (const float*)d_in[2];   // [64] f32
    float* out = (float*)d_out;

    const int M = in_sizes[0] / 128;            // total windows = B*L*N
    const long long xelems = (long long)M * 64;

    // Fill launched FIRST so ncu (-s 5 -c 1) captures the GEMM as launch #6.
    int rem = out_size - (int)xelems;
    if (rem > 0)
        fill_const_kernel<<<(rem + 255) / 256, 256>>>(out + xelems, rem, 128.0f);

    const int smem_bytes = 64 * 64 * (int)sizeof(float2)
                         + 2 * 8 * ASTRIDE * (int)sizeof(float4);
    cudaFuncSetAttribute(ecg_tok_gemm, cudaFuncAttributeMaxDynamicSharedMemorySize,
                         smem_bytes);
    ecg_tok_gemm<<<M / BM, THREADS, smem_bytes>>>(ecg, W, b, out);
}

// round 5
// speedup vs baseline: 2.6001x; 2.2636x over previous
#include <cuda_runtime.h>
#include <cstdint>

// out[m][d] = sum_k ecg[m*128+k] * W[d*128+k] + b[d],  M=196608, K=128, N=64.
// bf16-split tensor-core GEMM via mma.sync.m16n8k16:
//   D = Ahi*Whi + Alo*Whi + Ahi*Wlo  (fp32 accum), rel err ~1e-5.
// A fragments loaded directly from global (no smem staging); W hi/lo in smem.

#define THREADS 256
#define BM 128
#define WPAD 136          // bf16 per padded W row (272 B -> conflict-free ldmatrix)

__device__ __forceinline__ uint32_t s2u(const void* p) {
    uint32_t a;
    asm("{ .reg .u64 t; cvta.to.shared.u64 t, %1; cvt.u32.u64 %0, t; }" : "=r"(a) : "l"(p));
    return a;
}

// split float2 -> packed bf16x2 hi and lo (residual)
__device__ __forceinline__ void split2(float x, float y, uint32_t& hi, uint32_t& lo) {
    asm("cvt.rn.bf16x2.f32 %0, %1, %2;" : "=r"(hi) : "f"(y), "f"(x));
    float hx = __uint_as_float(hi << 16);
    float hy = __uint_as_float(hi & 0xffff0000u);
    float lx = x - hx, ly = y - hy;
    asm("cvt.rn.bf16x2.f32 %0, %1, %2;" : "=r"(lo) : "f"(ly), "f"(lx));
}

__device__ __forceinline__ void ldsm4(uint32_t& r0, uint32_t& r1, uint32_t& r2,
                                      uint32_t& r3, uint32_t addr) {
    asm volatile("ldmatrix.sync.aligned.m8n8.x4.shared.b16 {%0,%1,%2,%3}, [%4];"
                 : "=r"(r0), "=r"(r1), "=r"(r2), "=r"(r3) : "r"(addr));
}

__device__ __forceinline__ void mma16816(float& c0, float& c1, float& c2, float& c3,
                                         uint32_t a0, uint32_t a1, uint32_t a2, uint32_t a3,
                                         uint32_t b0, uint32_t b1) {
    asm volatile(
        "mma.sync.aligned.m16n8k16.row.col.f32.bf16.bf16.f32 "
        "{%0,%1,%2,%3}, {%4,%5,%6,%7}, {%8,%9}, {%0,%1,%2,%3};"
        : "+f"(c0), "+f"(c1), "+f"(c2), "+f"(c3)
        : "r"(a0), "r"(a1), "r"(a2), "r"(a3), "r"(b0), "r"(b1));
}

__global__ __launch_bounds__(THREADS, 2)
void ecg_tok_mma(const float* __restrict__ ecg,
                 const float* __restrict__ W,
                 const float* __restrict__ bias,
                 float* __restrict__ out) {
    __shared__ __align__(16) uint16_t WhiS[64 * WPAD];
    __shared__ __align__(16) uint16_t WloS[64 * WPAD];

    const int tid  = threadIdx.x;
    const int warp = tid >> 5;
    const int lane = tid & 31;
    const long long m0 = (long long)blockIdx.x * BM;

    // ---- prologue: load + split W into smem (64 rows x 128 k) ----
    #pragma unroll
    for (int it = 0; it < 8; it++) {
        int idx = tid + it * THREADS;      // 0..2047 float4s
        int n  = idx >> 5;
        int k4 = (idx & 31) * 4;
        float4 v = *reinterpret_cast<const float4*>(W + n * 128 + k4);
        uint32_t h0, l0, h1, l1;
        split2(v.x, v.y, h0, l0);
        split2(v.z, v.w, h1, l1);
        *reinterpret_cast<uint2*>(&WhiS[n * WPAD + k4]) = make_uint2(h0, h1);
        *reinterpret_cast<uint2*>(&WloS[n * WPAD + k4]) = make_uint2(l0, l1);
    }
    __syncthreads();

    // ldmatrix lane address term: row = (l/16)*8 + l%8, kofs = ((l/8)%2)*8 bf16
    const int lm_row  = ((lane >> 4) << 3) + (lane & 7);
    const int lm_kofs = ((lane >> 3) & 1) << 4;              // bytes
    const uint32_t lm_term = (uint32_t)(lm_row * (WPAD * 2) + lm_kofs);
    const uint32_t whi_base = s2u(WhiS) + lm_term;
    const uint32_t wlo_base = s2u(WloS) + lm_term;

    // A fragment global base: row = m0 + warp*16 + lane/4, col pair 2*(lane%4)
    const int arow = warp * 16 + (lane >> 2);
    const float* abase = ecg + (m0 + arow) * 128 + 2 * (lane & 3);

    float acc[8][4];
    #pragma unroll
    for (int nt = 0; nt < 8; nt++)
        #pragma unroll
        for (int j = 0; j < 4; j++) acc[nt][j] = 0.0f;

    #pragma unroll
    for (int s = 0; s < 8; s++) {           // k-step: k0 = 16*s
        const int k0 = 16 * s;

        // A: 4 float2 loads -> hi/lo fragments {a0,a1,a2,a3}
        float2 a00 = *reinterpret_cast<const float2*>(abase + k0);            // row, k
        float2 a10 = *reinterpret_cast<const float2*>(abase + 8 * 128 + k0);  // row+8, k
        float2 a01 = *reinterpret_cast<const float2*>(abase + k0 + 8);        // row, k+8
        float2 a11 = *reinterpret_cast<const float2*>(abase + 8 * 128 + k0 + 8);

        uint32_t ah[4], al[4];
        split2(a00.x, a00.y, ah[0], al[0]);
        split2(a10.x, a10.y, ah[1], al[1]);
        split2(a01.x, a01.y, ah[2], al[2]);
        split2(a11.x, a11.y, ah[3], al[3]);

        #pragma unroll
        for (int ntp = 0; ntp < 4; ntp++) {   // n-tile pairs (2 tiles per ldmatrix.x4)
            uint32_t off = (uint32_t)(ntp * 16 * WPAD * 2 + k0 * 2);
            uint32_t bh0, bh1, bh2, bh3, bl0, bl1, bl2, bl3;
            ldsm4(bh0, bh1, bh2, bh3, whi_base + off);
            ldsm4(bl0, bl1, bl2, bl3, wlo_base + off);

            float* c0 = acc[2 * ntp];
            float* c1 = acc[2 * ntp + 1];
            // term 1: Ahi * Whi
            mma16816(c0[0], c0[1], c0[2], c0[3], ah[0], ah[1], ah[2], ah[3], bh0, bh1);
            mma16816(c1[0], c1[1], c1[2], c1[3], ah[0], ah[1], ah[2], ah[3], bh2, bh3);
            // term 2: Alo * Whi
            mma16816(c0[0], c0[1], c0[2], c0[3], al[0], al[1], al[2], al[3], bh0, bh1);
            mma16816(c1[0], c1[1], c1[2], c1[3], al[0], al[1], al[2], al[3], bh2, bh3);
            // term 3: Ahi * Wlo
            mma16816(c0[0], c0[1], c0[2], c0[3], ah[0], ah[1], ah[2], ah[3], bl0, bl1);
            mma16816(c1[0], c1[1], c1[2], c1[3], ah[0], ah[1], ah[2], ah[3], bl2, bl3);
        }
    }

    // ---- epilogue: add bias, store ----
    const int ncol = 2 * (lane & 3);
    float* orow0 = out + (m0 + arow) * 64;
    float* orow1 = orow0 + 8 * 64;
    #pragma unroll
    for (int nt = 0; nt < 8; nt++) {
        float2 bv = *reinterpret_cast<const float2*>(bias + nt * 8 + ncol);
        float2 o0, o1;
        o0.x = acc[nt][0] + bv.x;  o0.y = acc[nt][1] + bv.y;
        o1.x = acc[nt][2] + bv.x;  o1.y = acc[nt][3] + bv.y;
        *reinterpret_cast<float2*>(orow0 + nt * 8 + ncol) = o0;
        *reinterpret_cast<float2*>(orow1 + nt * 8 + ncol) = o1;
    }
}

__global__ void fill_const_kernel(float* __restrict__ p, int n, float v) {
    int i = blockIdx.x * blockDim.x + threadIdx.x;
    if (i < n) p[i] = v;
}

extern "C" void kernel_launch(void* const* d_in, const int* in_sizes, int n_in,
                              void* d_out, int out_size) {
    const float* ecg = (const float*)d_in[0];
    const float* W   = (const float*)d_in[1];
    const float* b   = (const float*)d_in[2];
    float* out = (float*)d_out;

    const int M = in_sizes[0] / 128;
    const long long xelems = (long long)M * 64;

    int rem = out_size - (int)xelems;
    if (rem > 0)
        fill_const_kernel<<<(rem + 255) / 256, 256>>>(out + xelems, rem, 128.0f);

    ecg_tok_mma<<<M / BM, THREADS>>>(ecg, W, b, out);
}

// round 6
// speedup vs baseline: 3.0231x; 1.1627x over previous
#include <cuda_runtime.h>
#include <cstdint>

// out[m][d] = sum_k ecg[m*128+k] * W[d*128+k] + b[d],  M=196608, K=128, N=64.
// bf16-split HMMA (mma.sync.m16n8k16): D = Ahi*Whi + Alo*Whi + Ahi*Wlo.
// K columns inside each 16-chunk are permuted identically on A and W so a
// lane's LDG.128 float4 splits directly into a0/a2 fragment registers.
// Warp m-tile = 32 rows; beat_intervals fill folded into this kernel.

#define THREADS 128
#define BM 128
#define WPAD 136   // bf16 per padded W row (272 B rows -> conflict-free ldmatrix)

__device__ __forceinline__ uint32_t s2u(const void* p) {
    uint32_t a;
    asm("{ .reg .u64 t; cvta.to.shared.u64 t, %1; cvt.u32.u64 %0, t; }" : "=r"(a) : "l"(p));
    return a;
}

// split (x,y) -> packed bf16x2 hi and lo (residual)
__device__ __forceinline__ void split2(float x, float y, uint32_t& hi, uint32_t& lo) {
    asm("cvt.rn.bf16x2.f32 %0, %1, %2;" : "=r"(hi) : "f"(y), "f"(x));
    float hx = __uint_as_float(hi << 16);
    float hy = __uint_as_float(hi & 0xffff0000u);
    float lx = x - hx, ly = y - hy;
    asm("cvt.rn.bf16x2.f32 %0, %1, %2;" : "=r"(lo) : "f"(ly), "f"(lx));
}

__device__ __forceinline__ void ldsm4(uint32_t& r0, uint32_t& r1, uint32_t& r2,
                                      uint32_t& r3, uint32_t addr) {
    asm volatile("ldmatrix.sync.aligned.m8n8.x4.shared.b16 {%0,%1,%2,%3}, [%4];"
                 : "=r"(r0), "=r"(r1), "=r"(r2), "=r"(r3) : "r"(addr));
}

__device__ __forceinline__ void mma16816(float* c,
                                         uint32_t a0, uint32_t a1, uint32_t a2, uint32_t a3,
                                         uint32_t b0, uint32_t b1) {
    asm volatile(
        "mma.sync.aligned.m16n8k16.row.col.f32.bf16.bf16.f32 "
        "{%0,%1,%2,%3}, {%4,%5,%6,%7}, {%8,%9}, {%0,%1,%2,%3};"
        : "+f"(c[0]), "+f"(c[1]), "+f"(c[2]), "+f"(c[3])
        : "r"(a0), "r"(a1), "r"(a2), "r"(a3), "r"(b0), "r"(b1));
}

__global__ __launch_bounds__(THREADS, 3)
void ecg_tok_mma(const float* __restrict__ ecg,
                 const float* __restrict__ W,
                 const float* __restrict__ bias,
                 float* __restrict__ out,
                 long long xelems, int fillCount) {
    __shared__ __align__(16) uint32_t Whi32[64 * WPAD / 2];
    __shared__ __align__(16) uint32_t Wlo32[64 * WPAD / 2];

    const int tid  = threadIdx.x;
    const int warp = tid >> 5;
    const int lane = tid & 31;
    const long long m0 = (long long)blockIdx.x * BM;

    // ---- folded fill: beat_intervals tail (blocks 0..ceil(fillCount/128)-1) ----
    {
        int fi = blockIdx.x * THREADS + tid;
        if (fi < fillCount) out[xelems + fi] = 128.0f;
    }

    // ---- prologue: load + split W, store with per-16-chunk column permutation ----
    // global pair g (cols 2g,2g+1 of chunk) -> slice pair (g>>1) + (g&1)*4.
    // Thread reads float4 = global pairs (2q, 2q+1) -> slice pairs q and q+4.
    #pragma unroll
    for (int it = 0; it < 16; it++) {
        int idx   = tid + it * THREADS;     // 0..2047
        int n     = idx >> 5;
        int r     = idx & 31;
        int chunk = r >> 2;
        int q     = r & 3;
        float4 v = *reinterpret_cast<const float4*>(W + n * 128 + chunk * 16 + q * 4);
        uint32_t h0, l0, h1, l1;
        split2(v.x, v.y, h0, l0);
        split2(v.z, v.w, h1, l1);
        int u = n * (WPAD / 2) + chunk * 8 + q;   // u32 index of slice pair q
        Whi32[u]     = h0;
        Whi32[u + 4] = h1;                        // slice pair q+4
        Wlo32[u]     = l0;
        Wlo32[u + 4] = l1;
    }
    __syncthreads();

    // ldmatrix lane addressing (same as R5): rows n within ntile-pair, 16B k-halves
    const int lm_row  = ((lane >> 4) << 3) + (lane & 7);
    const int lm_kofs = ((lane >> 3) & 1) << 4;   // bytes
    const uint32_t lm_term  = (uint32_t)(lm_row * (WPAD * 2) + lm_kofs);
    const uint32_t whi_base = s2u(Whi32) + lm_term;
    const uint32_t wlo_base = s2u(Wlo32) + lm_term;

    // A geometry: warp rows = warp*32 + {0..31}; lane reads float4 at col 4*(lane&3)
    const int arow = warp * 32 + (lane >> 2);
    const float* abase = ecg + (m0 + arow) * 128 + 4 * (lane & 3);

    float acc[2][8][4];
    #pragma unroll
    for (int f = 0; f < 2; f++)
        #pragma unroll
        for (int nt = 0; nt < 8; nt++)
            #pragma unroll
            for (int j = 0; j < 4; j++) acc[f][nt][j] = 0.0f;

    // prologue A load (s = 0): j -> row offset 8*j
    float4 cur[4];
    #pragma unroll
    for (int j = 0; j < 4; j++)
        cur[j] = *reinterpret_cast<const float4*>(abase + j * 8 * 128);

    #pragma unroll
    for (int s = 0; s < 8; s++) {
        // split current chunk: ah[2j] = a0-part (slice pair q), ah[2j+1] = a2-part
        uint32_t ah[8], al[8];
        #pragma unroll
        for (int j = 0; j < 4; j++) {
            split2(cur[j].x, cur[j].y, ah[2 * j],     al[2 * j]);
            split2(cur[j].z, cur[j].w, ah[2 * j + 1], al[2 * j + 1]);
        }

        // prefetch next chunk
        if (s < 7) {
            #pragma unroll
            for (int j = 0; j < 4; j++)
                cur[j] = *reinterpret_cast<const float4*>(
                    abase + (s + 1) * 16 + j * 8 * 128);
        }

        #pragma unroll
        for (int ntp = 0; ntp < 4; ntp++) {
            uint32_t off = (uint32_t)(ntp * 16 * WPAD * 2 + s * 32);
            uint32_t bh0, bh1, bh2, bh3, bl0, bl1, bl2, bl3;
            ldsm4(bh0, bh1, bh2, bh3, whi_base + off);
            ldsm4(bl0, bl1, bl2, bl3, wlo_base + off);

            #pragma unroll
            for (int f = 0; f < 2; f++) {
                // fragment f: a0=ah[4f], a1=ah[4f+2], a2=ah[4f+1], a3=ah[4f+3]
                float* c0 = acc[f][2 * ntp];
                float* c1 = acc[f][2 * ntp + 1];
                mma16816(c0, ah[4*f], ah[4*f+2], ah[4*f+1], ah[4*f+3], bh0, bh1);
                mma16816(c1, ah[4*f], ah[4*f+2], ah[4*f+1], ah[4*f+3], bh2, bh3);
                mma16816(c0, al[4*f], al[4*f+2], al[4*f+1], al[4*f+3], bh0, bh1);
                mma16816(c1, al[4*f], al[4*f+2], al[4*f+1], al[4*f+3], bh2, bh3);
                mma16816(c0, ah[4*f], ah[4*f+2], ah[4*f+1], ah[4*f+3], bl0, bl1);
                mma16816(c1, ah[4*f], ah[4*f+2], ah[4*f+1], ah[4*f+3], bl2, bl3);
            }
        }
    }

    // ---- epilogue: add bias, store ----
    const int ncol = 2 * (lane & 3);
    #pragma unroll
    for (int f = 0; f < 2; f++) {
        long long row0 = m0 + warp * 32 + f * 16 + (lane >> 2);
        float* orow0 = out + row0 * 64;
        float* orow1 = orow0 + 8 * 64;
        #pragma unroll
        for (int nt = 0; nt < 8; nt++) {
            float2 bv = *reinterpret_cast<const float2*>(bias + nt * 8 + ncol);
            float2 o0, o1;
            o0.x = acc[f][nt][0] + bv.x;  o0.y = acc[f][nt][1] + bv.y;
            o1.x = acc[f][nt][2] + bv.x;  o1.y = acc[f][nt][3] + bv.y;
            *reinterpret_cast<float2*>(orow0 + nt * 8 + ncol) = o0;
            *reinterpret_cast<float2*>(orow1 + nt * 8 + ncol) = o1;
        }
    }
}

extern "C" void kernel_launch(void* const* d_in, const int* in_sizes, int n_in,
                              void* d_out, int out_size) {
    const float* ecg = (const float*)d_in[0];
    const float* W   = (const float*)d_in[1];
    const float* b   = (const float*)d_in[2];
    float* out = (float*)d_out;

    const int M = in_sizes[0] / 128;
    const long long xelems = (long long)M * 64;
    const int fillCount = out_size - (int)xelems;   // 16384

    ecg_tok_mma<<<M / BM, THREADS>>>(ecg, W, b, out, xelems, fillCount);
}